// round 2
// baseline (speedup 1.0000x reference)
#include <cuda_runtime.h>
#include <cstddef>

// 2-layer LSTM (H=20) + FC head, B=4096, T=512, D=1.
// 4 lanes per sequence, 5 hidden units per lane, h exchanged via width-4 shuffles.
// Weights packed as gate-pairs (I,F)/(G,O) in shared -> LDS.128 + fma.rn.f32x2.

using u64 = unsigned long long;

__device__ __forceinline__ u64 fma2(u64 a, u64 b, u64 c) {
    u64 d;
    asm("fma.rn.f32x2 %0, %1, %2, %3;" : "=l"(d) : "l"(a), "l"(b), "l"(c));
    return d;
}
__device__ __forceinline__ u64 pk2(float lo, float hi) {
    u64 r;
    asm("mov.b64 %0, {%1, %2};" : "=l"(r) : "f"(lo), "f"(hi));
    return r;
}
__device__ __forceinline__ void up2(float& lo, float& hi, u64 v) {
    asm("mov.b64 {%0, %1}, %2;" : "=f"(lo), "=f"(hi) : "l"(v));
}

__device__ __forceinline__ float sigm_f(float x) {
    return __fdividef(1.0f, 1.0f + __expf(-x));
}
__device__ __forceinline__ float tanh_f(float x) {
    return __fdividef(2.0f, 1.0f + __expf(-2.0f * x)) - 1.0f;
}

// per-j strides (in u64 units), padded for bank-conflict-free 4-address access
#define J0_STRIDE 44   // layer0: [IF 20][GO 20][pad 4]   = 352 B
#define J1_STRIDE 84   // layer1: [uIF 20][uGO 20][vIF 20][vGO 20][pad 4] = 672 B

__global__ void __launch_bounds__(128, 1) lstm2_fc_kernel(
    const float* __restrict__ x,     // [B, T]
    const float* __restrict__ Wih0,  // [80, 1]
    const float* __restrict__ Whh0,  // [80, 20]
    const float* __restrict__ bih0,  // [80]
    const float* __restrict__ bhh0,  // [80]
    const float* __restrict__ Wih1,  // [80, 20]
    const float* __restrict__ Whh1,  // [80, 20]
    const float* __restrict__ bih1,  // [80]
    const float* __restrict__ bhh1,  // [80]
    const float* __restrict__ fcW,   // [1, 20]
    const float* __restrict__ fcb,   // [1]
    float* __restrict__ out,         // [B, 1]
    int Btot, int Tlen)
{
    __shared__ __align__(16) u64 sm0[20 * J0_STRIDE];  // packed Whh0
    __shared__ __align__(16) u64 sm1[20 * J1_STRIDE];  // packed Wih1|Whh1
    __shared__ __align__(16) u64 sw0[40];              // packed Wih0 (x weights)
    __shared__ __align__(16) u64 sb0[40];              // packed bih0+bhh0
    __shared__ __align__(16) u64 sb1[40];              // packed bih1+bhh1
    __shared__ float sFc[20];
    __shared__ float sFcb;

    const int tid = threadIdx.x;

    // ---- pack weights into shared ----
    // layer0 recurrent: pair p=0 -> rows (j, 20+j) = (I,F); p=1 -> (40+j, 60+j) = (G,O)
    for (int idx = tid; idx < 800; idx += 128) {
        int j = idx / 40, r = idx % 40, p = r / 20, m = r % 20;
        int rlo = p ? (40 + j) : j;
        int rhi = rlo + 20;
        sm0[j * J0_STRIDE + p * 20 + m] = pk2(Whh0[rlo * 20 + m], Whh0[rhi * 20 + m]);
    }
    // layer1: q=0 uIF, q=1 uGO, q=2 vIF, q=3 vGO
    for (int idx = tid; idx < 1600; idx += 128) {
        int j = idx / 80, r = idx % 80, q = r / 20, m = r % 20;
        const float* mat = (q < 2) ? Wih1 : Whh1;
        int p = q & 1;
        int rlo = p ? (40 + j) : j;
        int rhi = rlo + 20;
        sm1[j * J1_STRIDE + q * 20 + m] = pk2(mat[rlo * 20 + m], mat[rhi * 20 + m]);
    }
    for (int idx = tid; idx < 40; idx += 128) {
        int j = idx / 2, p = idx % 2;
        int rlo = p ? (40 + j) : j;
        int rhi = rlo + 20;
        sw0[j * 2 + p] = pk2(Wih0[rlo], Wih0[rhi]);
        sb0[j * 2 + p] = pk2(bih0[rlo] + bhh0[rlo], bih0[rhi] + bhh0[rhi]);
        sb1[j * 2 + p] = pk2(bih1[rlo] + bhh1[rlo], bih1[rhi] + bhh1[rhi]);
    }
    if (tid < 20) sFc[tid] = fcW[tid];
    if (tid == 0) sFcb = fcb[0];
    __syncthreads();

    // ---- lane/group mapping ----
    const int grp = tid >> 2;
    const int sub = tid & 3;
    int b = blockIdx.x * 32 + grp;
    const bool active = (b < Btot);
    if (b >= Btot) b = Btot - 1;
    const float* xb = x + (size_t)b * Tlen;

    float c0[5], c1[5], h0s[5], h1s[5];
    #pragma unroll
    for (int i = 0; i < 5; ++i) { c0[i] = 0.f; c1[i] = 0.f; h0s[i] = 0.f; h1s[i] = 0.f; }

    u64 hh2[20], hb2[20];  // (h,h) packed, full vectors
    #pragma unroll
    for (int i = 0; i < 20; ++i) { hh2[i] = 0ull; hb2[i] = 0ull; }

    const unsigned FULL = 0xffffffffu;
    const int jbase = sub * 5;

    float xt_next = __ldg(&xb[0]);

    #pragma unroll 1
    for (int t = 0; t < Tlen; ++t) {
        const float xt = xt_next;
        if (t + 1 < Tlen) xt_next = __ldg(&xb[t + 1]);
        const u64 xt2 = pk2(xt, xt);

        // ---------------- layer 0 ----------------
        #pragma unroll
        for (int jl = 0; jl < 5; ++jl) {
            const int j = jbase + jl;
            const u64* base = &sm0[j * J0_STRIDE];
            u64 aIF = fma2(sw0[j * 2 + 0], xt2, sb0[j * 2 + 0]);
            u64 aGO = fma2(sw0[j * 2 + 1], xt2, sb0[j * 2 + 1]);
            #pragma unroll
            for (int mq = 0; mq < 10; ++mq) {
                ulonglong2 wIF = *reinterpret_cast<const ulonglong2*>(base + mq * 2);
                ulonglong2 wGO = *reinterpret_cast<const ulonglong2*>(base + 20 + mq * 2);
                aIF = fma2(wIF.x, hh2[2 * mq],     aIF);
                aGO = fma2(wGO.x, hh2[2 * mq],     aGO);
                aIF = fma2(wIF.y, hh2[2 * mq + 1], aIF);
                aGO = fma2(wGO.y, hh2[2 * mq + 1], aGO);
            }
            float gi, gf, gg, go;
            up2(gi, gf, aIF);
            up2(gg, go, aGO);
            const float ai = sigm_f(gi);
            const float af = sigm_f(gf);
            const float ag = tanh_f(gg);
            const float ao = sigm_f(go);
            const float cn = fmaf(af, c0[jl], ai * ag);
            c0[jl] = cn;
            h0s[jl] = ao * tanh_f(cn);
        }

        // gather full h0 across the group (packed duplicated)
        #pragma unroll
        for (int mt = 0; mt < 4; ++mt)
            #pragma unroll
            for (int mi = 0; mi < 5; ++mi) {
                float v = __shfl_sync(FULL, h0s[mi], mt, 4);
                hh2[mt * 5 + mi] = pk2(v, v);
            }

        // ---------------- layer 1 ----------------
        #pragma unroll
        for (int jl = 0; jl < 5; ++jl) {
            const int j = jbase + jl;
            const u64* base = &sm1[j * J1_STRIDE];
            u64 aIF = sb1[j * 2 + 0];
            u64 aGO = sb1[j * 2 + 1];
            #pragma unroll
            for (int mq = 0; mq < 10; ++mq) {
                ulonglong2 uIF = *reinterpret_cast<const ulonglong2*>(base +      mq * 2);
                ulonglong2 uGO = *reinterpret_cast<const ulonglong2*>(base + 20 + mq * 2);
                ulonglong2 vIF = *reinterpret_cast<const ulonglong2*>(base + 40 + mq * 2);
                ulonglong2 vGO = *reinterpret_cast<const ulonglong2*>(base + 60 + mq * 2);
                aIF = fma2(uIF.x, hh2[2 * mq],     aIF);
                aGO = fma2(uGO.x, hh2[2 * mq],     aGO);
                aIF = fma2(uIF.y, hh2[2 * mq + 1], aIF);
                aGO = fma2(uGO.y, hh2[2 * mq + 1], aGO);
                aIF = fma2(vIF.x, hb2[2 * mq],     aIF);
                aGO = fma2(vGO.x, hb2[2 * mq],     aGO);
                aIF = fma2(vIF.y, hb2[2 * mq + 1], aIF);
                aGO = fma2(vGO.y, hb2[2 * mq + 1], aGO);
            }
            float gi, gf, gg, go;
            up2(gi, gf, aIF);
            up2(gg, go, aGO);
            const float ai = sigm_f(gi);
            const float af = sigm_f(gf);
            const float ag = tanh_f(gg);
            const float ao = sigm_f(go);
            const float cn = fmaf(af, c1[jl], ai * ag);
            c1[jl] = cn;
            h1s[jl] = ao * tanh_f(cn);
        }

        // gather full h1 for next step
        #pragma unroll
        for (int mt = 0; mt < 4; ++mt)
            #pragma unroll
            for (int mi = 0; mi < 5; ++mi) {
                float v = __shfl_sync(FULL, h1s[mi], mt, 4);
                hb2[mt * 5 + mi] = pk2(v, v);
            }
    }

    // FC head
    float p = 0.f;
    #pragma unroll
    for (int jl = 0; jl < 5; ++jl)
        p = fmaf(sFc[jbase + jl], h1s[jl], p);
    p += __shfl_xor_sync(FULL, p, 1, 4);
    p += __shfl_xor_sync(FULL, p, 2, 4);
    if (active && sub == 0)
        out[b] = p + sFcb;
}

extern "C" void kernel_launch(void* const* d_in, const int* in_sizes, int n_in,
                              void* d_out, int out_size)
{
    const float* x    = (const float*)d_in[0];
    const float* Wih0 = (const float*)d_in[1];
    const float* Whh0 = (const float*)d_in[2];
    const float* bih0 = (const float*)d_in[3];
    const float* bhh0 = (const float*)d_in[4];
    const float* Wih1 = (const float*)d_in[5];
    const float* Whh1 = (const float*)d_in[6];
    const float* bih1 = (const float*)d_in[7];
    const float* bhh1 = (const float*)d_in[8];
    const float* fcW  = (const float*)d_in[9];
    const float* fcb  = (const float*)d_in[10];

    const int B = out_size;            // out is [B, 1] fp32
    const int T = in_sizes[0] / B;     // x is [B, T, 1]
    const int blocks = (B + 31) / 32;  // 32 sequences per 128-thread block

    lstm2_fc_kernel<<<blocks, 128>>>(x, Wih0, Whh0, bih0, bhh0,
                                     Wih1, Whh1, bih1, bhh1,
                                     fcW, fcb, (float*)d_out, B, T);
}

// round 3
// speedup vs baseline: 1.0576x; 1.0576x over previous
#include <cuda_runtime.h>
#include <cstddef>

// 2-layer LSTM (H=20) + FC head, B=4096, T=512, D=1.
// 4 lanes per sequence, 5 hidden units per lane, h exchanged via width-4 shuffles.
// Weights packed as gate-pairs (I,F)/(G,O) in shared -> LDS.128 + fma.rn.f32x2.

using u64 = unsigned long long;

__device__ __forceinline__ u64 fma2(u64 a, u64 b, u64 c) {
    u64 d;
    asm("fma.rn.f32x2 %0, %1, %2, %3;" : "=l"(d) : "l"(a), "l"(b), "l"(c));
    return d;
}
__device__ __forceinline__ u64 pk2(float lo, float hi) {
    u64 r;
    asm("mov.b64 %0, {%1, %2};" : "=l"(r) : "f"(lo), "f"(hi));
    return r;
}
__device__ __forceinline__ void up2(float& lo, float& hi, u64 v) {
    asm("mov.b64 {%0, %1}, %2;" : "=f"(lo), "=f"(hi) : "l"(v));
}

__device__ __forceinline__ float sigm_f(float x) {
    return __fdividef(1.0f, 1.0f + __expf(-x));
}
__device__ __forceinline__ float tanh_f(float x) {
    return __fdividef(2.0f, 1.0f + __expf(-2.0f * x)) - 1.0f;
}

// per-j strides (in u64 units), padded for bank-conflict-free 4-address access
#define J0_STRIDE 44   // layer0: [IF 20][GO 20][pad 4]   = 352 B
#define J1_STRIDE 84   // layer1: [uIF 20][uGO 20][vIF 20][vGO 20][pad 4] = 672 B

__global__ void __launch_bounds__(128, 1) lstm2_fc_kernel(
    const float* __restrict__ x,     // [B, T]
    const float* __restrict__ Wih0,  // [80, 1]
    const float* __restrict__ Whh0,  // [80, 20]
    const float* __restrict__ bih0,  // [80]
    const float* __restrict__ bhh0,  // [80]
    const float* __restrict__ Wih1,  // [80, 20]
    const float* __restrict__ Whh1,  // [80, 20]
    const float* __restrict__ bih1,  // [80]
    const float* __restrict__ bhh1,  // [80]
    const float* __restrict__ fcW,   // [1, 20]
    const float* __restrict__ fcb,   // [1]
    float* __restrict__ out,         // [B, 1]
    int Btot, int Tlen)
{
    __shared__ __align__(16) u64 sm0[20 * J0_STRIDE];  // packed Whh0
    __shared__ __align__(16) u64 sm1[20 * J1_STRIDE];  // packed Wih1|Whh1
    __shared__ __align__(16) u64 sw0[40];              // packed Wih0 (x weights)
    __shared__ __align__(16) u64 sb0[40];              // packed bih0+bhh0
    __shared__ __align__(16) u64 sb1[40];              // packed bih1+bhh1
    __shared__ float sFc[20];
    __shared__ float sFcb;

    const int tid = threadIdx.x;

    // ---- pack weights into shared ----
    // layer0 recurrent: pair p=0 -> rows (j, 20+j) = (I,F); p=1 -> (40+j, 60+j) = (G,O)
    for (int idx = tid; idx < 800; idx += 128) {
        int j = idx / 40, r = idx % 40, p = r / 20, m = r % 20;
        int rlo = p ? (40 + j) : j;
        int rhi = rlo + 20;
        sm0[j * J0_STRIDE + p * 20 + m] = pk2(Whh0[rlo * 20 + m], Whh0[rhi * 20 + m]);
    }
    // layer1: q=0 uIF, q=1 uGO, q=2 vIF, q=3 vGO
    for (int idx = tid; idx < 1600; idx += 128) {
        int j = idx / 80, r = idx % 80, q = r / 20, m = r % 20;
        const float* mat = (q < 2) ? Wih1 : Whh1;
        int p = q & 1;
        int rlo = p ? (40 + j) : j;
        int rhi = rlo + 20;
        sm1[j * J1_STRIDE + q * 20 + m] = pk2(mat[rlo * 20 + m], mat[rhi * 20 + m]);
    }
    for (int idx = tid; idx < 40; idx += 128) {
        int j = idx / 2, p = idx % 2;
        int rlo = p ? (40 + j) : j;
        int rhi = rlo + 20;
        sw0[j * 2 + p] = pk2(Wih0[rlo], Wih0[rhi]);
        sb0[j * 2 + p] = pk2(bih0[rlo] + bhh0[rlo], bih0[rhi] + bhh0[rhi]);
        sb1[j * 2 + p] = pk2(bih1[rlo] + bhh1[rlo], bih1[rhi] + bhh1[rhi]);
    }
    if (tid < 20) sFc[tid] = fcW[tid];
    if (tid == 0) sFcb = fcb[0];
    __syncthreads();

    // ---- lane/group mapping ----
    const int grp = tid >> 2;
    const int sub = tid & 3;
    int b = blockIdx.x * 32 + grp;
    const bool active = (b < Btot);
    if (b >= Btot) b = Btot - 1;
    const float* xb = x + (size_t)b * Tlen;

    float c0[5], c1[5], h0s[5], h1s[5];
    #pragma unroll
    for (int i = 0; i < 5; ++i) { c0[i] = 0.f; c1[i] = 0.f; h0s[i] = 0.f; h1s[i] = 0.f; }

    u64 hh2[20], hb2[20];  // (h,h) packed, full vectors
    #pragma unroll
    for (int i = 0; i < 20; ++i) { hh2[i] = 0ull; hb2[i] = 0ull; }

    const unsigned FULL = 0xffffffffu;
    const int jbase = sub * 5;

    float xt_next = __ldg(&xb[0]);

    #pragma unroll 1
    for (int t = 0; t < Tlen; ++t) {
        const float xt = xt_next;
        if (t + 1 < Tlen) xt_next = __ldg(&xb[t + 1]);
        const u64 xt2 = pk2(xt, xt);

        // ---------------- layer 0 ----------------
        #pragma unroll
        for (int jl = 0; jl < 5; ++jl) {
            const int j = jbase + jl;
            const u64* base = &sm0[j * J0_STRIDE];
            u64 aIF = fma2(sw0[j * 2 + 0], xt2, sb0[j * 2 + 0]);
            u64 aGO = fma2(sw0[j * 2 + 1], xt2, sb0[j * 2 + 1]);
            #pragma unroll
            for (int mq = 0; mq < 10; ++mq) {
                ulonglong2 wIF = *reinterpret_cast<const ulonglong2*>(base + mq * 2);
                ulonglong2 wGO = *reinterpret_cast<const ulonglong2*>(base + 20 + mq * 2);
                aIF = fma2(wIF.x, hh2[2 * mq],     aIF);
                aGO = fma2(wGO.x, hh2[2 * mq],     aGO);
                aIF = fma2(wIF.y, hh2[2 * mq + 1], aIF);
                aGO = fma2(wGO.y, hh2[2 * mq + 1], aGO);
            }
            float gi, gf, gg, go;
            up2(gi, gf, aIF);
            up2(gg, go, aGO);
            const float ai = sigm_f(gi);
            const float af = sigm_f(gf);
            const float ag = tanh_f(gg);
            const float ao = sigm_f(go);
            const float cn = fmaf(af, c0[jl], ai * ag);
            c0[jl] = cn;
            h0s[jl] = ao * tanh_f(cn);
        }

        // gather full h0 across the group (packed duplicated)
        #pragma unroll
        for (int mt = 0; mt < 4; ++mt)
            #pragma unroll
            for (int mi = 0; mi < 5; ++mi) {
                float v = __shfl_sync(FULL, h0s[mi], mt, 4);
                hh2[mt * 5 + mi] = pk2(v, v);
            }

        // ---------------- layer 1 ----------------
        #pragma unroll
        for (int jl = 0; jl < 5; ++jl) {
            const int j = jbase + jl;
            const u64* base = &sm1[j * J1_STRIDE];
            u64 aIF = sb1[j * 2 + 0];
            u64 aGO = sb1[j * 2 + 1];
            #pragma unroll
            for (int mq = 0; mq < 10; ++mq) {
                ulonglong2 uIF = *reinterpret_cast<const ulonglong2*>(base +      mq * 2);
                ulonglong2 uGO = *reinterpret_cast<const ulonglong2*>(base + 20 + mq * 2);
                ulonglong2 vIF = *reinterpret_cast<const ulonglong2*>(base + 40 + mq * 2);
                ulonglong2 vGO = *reinterpret_cast<const ulonglong2*>(base + 60 + mq * 2);
                aIF = fma2(uIF.x, hh2[2 * mq],     aIF);
                aGO = fma2(uGO.x, hh2[2 * mq],     aGO);
                aIF = fma2(uIF.y, hh2[2 * mq + 1], aIF);
                aGO = fma2(uGO.y, hh2[2 * mq + 1], aGO);
                aIF = fma2(vIF.x, hb2[2 * mq],     aIF);
                aGO = fma2(vGO.x, hb2[2 * mq],     aGO);
                aIF = fma2(vIF.y, hb2[2 * mq + 1], aIF);
                aGO = fma2(vGO.y, hb2[2 * mq + 1], aGO);
            }
            float gi, gf, gg, go;
            up2(gi, gf, aIF);
            up2(gg, go, aGO);
            const float ai = sigm_f(gi);
            const float af = sigm_f(gf);
            const float ag = tanh_f(gg);
            const float ao = sigm_f(go);
            const float cn = fmaf(af, c1[jl], ai * ag);
            c1[jl] = cn;
            h1s[jl] = ao * tanh_f(cn);
        }

        // gather full h1 for next step
        #pragma unroll
        for (int mt = 0; mt < 4; ++mt)
            #pragma unroll
            for (int mi = 0; mi < 5; ++mi) {
                float v = __shfl_sync(FULL, h1s[mi], mt, 4);
                hb2[mt * 5 + mi] = pk2(v, v);
            }
    }

    // FC head
    float p = 0.f;
    #pragma unroll
    for (int jl = 0; jl < 5; ++jl)
        p = fmaf(sFc[jbase + jl], h1s[jl], p);
    p += __shfl_xor_sync(FULL, p, 1, 4);
    p += __shfl_xor_sync(FULL, p, 2, 4);
    if (active && sub == 0)
        out[b] = p + sFcb;
}

extern "C" void kernel_launch(void* const* d_in, const int* in_sizes, int n_in,
                              void* d_out, int out_size)
{
    const float* x    = (const float*)d_in[0];
    const float* Wih0 = (const float*)d_in[1];
    const float* Whh0 = (const float*)d_in[2];
    const float* bih0 = (const float*)d_in[3];
    const float* bhh0 = (const float*)d_in[4];
    const float* Wih1 = (const float*)d_in[5];
    const float* Whh1 = (const float*)d_in[6];
    const float* bih1 = (const float*)d_in[7];
    const float* bhh1 = (const float*)d_in[8];
    const float* fcW  = (const float*)d_in[9];
    const float* fcb  = (const float*)d_in[10];

    const int B = out_size;            // out is [B, 1] fp32
    const int T = in_sizes[0] / B;     // x is [B, T, 1]
    const int blocks = (B + 31) / 32;  // 32 sequences per 128-thread block

    lstm2_fc_kernel<<<blocks, 128>>>(x, Wih0, Whh0, bih0, bhh0,
                                     Wih1, Whh1, bih1, bhh1,
                                     fcW, fcb, (float*)d_out, B, T);
}